// round 6
// baseline (speedup 1.0000x reference)
#include <cuda_runtime.h>
#include <cuda_bf16.h>

#define BB    2
#define NSEQ  2048
#define DIMX  1024
#define HH    16
#define DD    64
#define QKVS  3072
#define GM    4096
#define GN    3072
#define GK    1024

// bf16 hi/lo split scratch (precomputed inputs + QKV projection output)
__device__ __nv_bfloat16 g_xh[(size_t)GM * GK], g_xl[(size_t)GM * GK];
__device__ __nv_bfloat16 g_wh[(size_t)GN * GK], g_wl[(size_t)GN * GK];
__device__ __nv_bfloat16 g_sh[(size_t)GM * GN], g_sl[(size_t)GM * GN];

// ---------------------------------------------------------------------------
// portable PTX helpers (sm_80 feature set only)
// ---------------------------------------------------------------------------
__device__ __forceinline__ unsigned smem_u32(const void* p) {
    unsigned a;
    asm("{ .reg .u64 t; cvta.to.shared.u64 t, %1; cvt.u32.u64 %0, t; }" : "=r"(a) : "l"(p));
    return a;
}
__device__ __forceinline__ void ldsm4(unsigned* r, unsigned a) {
    asm volatile("ldmatrix.sync.aligned.m8n8.x4.shared.b16 {%0,%1,%2,%3}, [%4];"
                 : "=r"(r[0]), "=r"(r[1]), "=r"(r[2]), "=r"(r[3]) : "r"(a));
}
__device__ __forceinline__ void ldsm4t(unsigned* r, unsigned a) {
    asm volatile("ldmatrix.sync.aligned.m8n8.x4.trans.shared.b16 {%0,%1,%2,%3}, [%4];"
                 : "=r"(r[0]), "=r"(r[1]), "=r"(r[2]), "=r"(r[3]) : "r"(a));
}
__device__ __forceinline__ void mmab(float* c, const unsigned* a, unsigned b0, unsigned b1) {
    asm volatile("mma.sync.aligned.m16n8k16.row.col.f32.bf16.bf16.f32 "
                 "{%0,%1,%2,%3}, {%4,%5,%6,%7}, {%8,%9}, {%0,%1,%2,%3};"
                 : "+f"(c[0]), "+f"(c[1]), "+f"(c[2]), "+f"(c[3])
                 : "r"(a[0]), "r"(a[1]), "r"(a[2]), "r"(a[3]), "r"(b0), "r"(b1));
}
__device__ __forceinline__ void split2(float a, float b, __nv_bfloat162& h, __nv_bfloat162& l) {
    h = __float22bfloat162_rn(make_float2(a, b));
    l = __float22bfloat162_rn(make_float2(a - __bfloat162float(h.x), b - __bfloat162float(h.y)));
}
#define CPA(dst, src) \
    asm volatile("cp.async.cg.shared.global [%0], [%1], 16;" :: "r"(dst), "l"(src))
#define CPA_COMMIT() asm volatile("cp.async.commit_group;" ::: "memory")
template <int N>
__device__ __forceinline__ void cpa_wait() {
    asm volatile("cp.async.wait_group %0;" :: "n"(N) : "memory");
}

// ---------------------------------------------------------------------------
// Kernel 0: fp32 -> bf16 hi/lo split (layout-preserving)
// ---------------------------------------------------------------------------
__global__ __launch_bounds__(256) void split_kernel(const float* __restrict__ src,
                                                    __nv_bfloat16* __restrict__ hi,
                                                    __nv_bfloat16* __restrict__ lo, int n4) {
    int i = blockIdx.x * 256 + threadIdx.x;
    if (i >= n4) return;
    float4 v = ((const float4*)src)[i];
    __nv_bfloat162 h0, l0, h1, l1;
    split2(v.x, v.y, h0, l0);
    split2(v.z, v.w, h1, l1);
    ((__nv_bfloat162*)hi)[i * 2 + 0] = h0;
    ((__nv_bfloat162*)hi)[i * 2 + 1] = h1;
    ((__nv_bfloat162*)lo)[i * 2 + 0] = l0;
    ((__nv_bfloat162*)lo)[i * 2 + 1] = l1;
}

// ---------------------------------------------------------------------------
// Kernel 1: QKV GEMM, bf16 3-term split, cp.async 2-stage pipeline.
// CTA 128x128, K-chunk 32. 8 warps = 4(m) x 2(n), warp tile 32x64.
// Stage (40960 B): Ah 0, Al 10240, Bh 20480, Bl 30720; pitch 80 B.
// ---------------------------------------------------------------------------
#define GSTG 40960
__global__ __launch_bounds__(256, 2) void qkv_gemm() {
    extern __shared__ __align__(16) unsigned char gs[];
    const unsigned sb = smem_u32(gs);
    const int tid = threadIdx.x, lane = tid & 31, wid = tid >> 5;
    const int wm = wid & 3, wn = wid >> 2;
    const int bm = blockIdx.y * 128, bn = blockIdx.x * 128;

    float acc[2][8][4];
#pragma unroll
    for (int i = 0; i < 2; i++)
#pragma unroll
        for (int j = 0; j < 8; j++)
#pragma unroll
            for (int q = 0; q < 4; q++) acc[i][j][q] = 0.f;

    const int lrow = tid >> 1, lh = (tid & 1) * 16;
    const __nv_bfloat16* xh = g_xh + (size_t)(bm + lrow) * GK + lh;
    const __nv_bfloat16* xl = g_xl + (size_t)(bm + lrow) * GK + lh;
    const __nv_bfloat16* wh = g_wh + (size_t)(bn + lrow) * GK + lh;
    const __nv_bfloat16* wl = g_wl + (size_t)(bn + lrow) * GK + lh;
    const unsigned drow = lrow * 80 + lh * 2;   // dst byte offset within array

    auto issue = [&](int c, int s) {
        const unsigned st = sb + s * GSTG + drow;
        const int ko = c * 32;
        CPA(st,                 xh + ko);  CPA(st + 16,             xh + ko + 8);
        CPA(st + 10240,         xl + ko);  CPA(st + 10240 + 16,     xl + ko + 8);
        CPA(st + 20480,         wh + ko);  CPA(st + 20480 + 16,     wh + ko + 8);
        CPA(st + 30720,         wl + ko);  CPA(st + 30720 + 16,     wl + ko + 8);
        CPA_COMMIT();
    };

    const unsigned aOff = (unsigned)((wm * 32 + (lane & 15)) * 80 + (lane >> 4) * 16);
    const unsigned bOff = 20480 + (unsigned)((wn * 64 + (lane & 7) + ((lane >> 4) << 3)) * 80 +
                                             ((lane >> 3) & 1) * 16);

    issue(0, 0);
    for (int c = 0; c < 32; c++) {
        if (c < 31) { issue(c + 1, (c + 1) & 1); cpa_wait<1>(); }
        else        { cpa_wait<0>(); }
        __syncthreads();
        const unsigned st = sb + (c & 1) * GSTG;
        const unsigned aAddr = st + aOff, bAddr = st + bOff;
#pragma unroll
        for (int s = 0; s < 2; s++) {
            unsigned ah[2][4], al[2][4];
            ldsm4(ah[0], aAddr + s * 32);
            ldsm4(ah[1], aAddr + 1280 + s * 32);
            ldsm4(al[0], aAddr + 10240 + s * 32);
            ldsm4(al[1], aAddr + 10240 + 1280 + s * 32);
#pragma unroll
            for (int np = 0; np < 4; np++) {
                unsigned bh[4], bl[4];
                ldsm4(bh, bAddr + np * 1280 + s * 32);
                ldsm4(bl, bAddr + 10240 + np * 1280 + s * 32);
#pragma unroll
                for (int mt = 0; mt < 2; mt++) {
                    mmab(acc[mt][2 * np + 0], ah[mt], bh[0], bh[1]);
                    mmab(acc[mt][2 * np + 0], ah[mt], bl[0], bl[1]);
                    mmab(acc[mt][2 * np + 0], al[mt], bh[0], bh[1]);
                    mmab(acc[mt][2 * np + 1], ah[mt], bh[2], bh[3]);
                    mmab(acc[mt][2 * np + 1], ah[mt], bl[2], bl[3]);
                    mmab(acc[mt][2 * np + 1], al[mt], bh[2], bh[3]);
                }
            }
        }
        __syncthreads();
    }

#pragma unroll
    for (int mt = 0; mt < 2; mt++) {
        int m = bm + wm * 32 + mt * 16 + (lane >> 2);
#pragma unroll
        for (int nt = 0; nt < 8; nt++) {
            int gc = bn + wn * 64 + nt * 8 + ((lane & 3) << 1);
            float sc = (gc < DIMX) ? 0.125f : 1.0f;
            __nv_bfloat162 h, l;
            split2(acc[mt][nt][0] * sc, acc[mt][nt][1] * sc, h, l);
            *(__nv_bfloat162*)(g_sh + (size_t)m * GN + gc) = h;
            *(__nv_bfloat162*)(g_sl + (size_t)m * GN + gc) = l;
            split2(acc[mt][nt][2] * sc, acc[mt][nt][3] * sc, h, l);
            *(__nv_bfloat162*)(g_sh + (size_t)(m + 8) * GN + gc) = h;
            *(__nv_bfloat162*)(g_sl + (size_t)(m + 8) * GN + gc) = l;
        }
    }
}

// ---------------------------------------------------------------------------
// Kernel 2: attention. CTA = (b, h, 128 Q rows); 8 warps = 4 row-groups(32
// rows) x 2 j-halves(32). Each warp: 2 row-tiles of 16 -> K/V frags reused 2x.
// cp.async double-buffered K/V. 3-term bf16 mma; exp without max-subtraction;
// O in regs; cross-half smem reduce at end.
// smem bytes: Qh 0, Ql 18432, KV stage s at 36864+s*36864
//   (Kh +0, Kl +9216, Vh +18432, Vl +27648), Ph 110592, Pl 129024. Tot 147456.
// ---------------------------------------------------------------------------
#define ASTG 36864
__global__ __launch_bounds__(256) void attn(float* __restrict__ out) {
    extern __shared__ __align__(16) unsigned char sm_raw[];
    const unsigned sb = smem_u32(sm_raw);
    const int tid = threadIdx.x, lane = tid & 31, wid = tid >> 5;
    const int g = wid & 3, js = wid >> 2;
    const int b = blockIdx.z, h = blockIdx.y, q0 = blockIdx.x * 128;

    // ---- Q tile load (128 rows, hi/lo), plain LDG/STS (once) ----
    {
        int row = tid >> 1, c0 = (tid & 1) * 32;
        size_t go = (size_t)(b * NSEQ + q0 + row) * QKVS + h * 64 + c0;
        unsigned d = (unsigned)((row * 72 + c0) * 2);
#pragma unroll
        for (int p = 0; p < 4; p++) {
            *(uint4*)(sm_raw + d + p * 16)         = *(const uint4*)(g_sh + go + p * 8);
            *(uint4*)(sm_raw + 18432 + d + p * 16) = *(const uint4*)(g_sl + go + p * 8);
        }
    }

    // ---- K/V cp.async issue helper ----
    const int krow = tid >> 2, kq = (tid & 3) * 16;
    const size_t kvb = (size_t)(b * NSEQ + krow) * QKVS + h * 64 + kq;
    const unsigned kvd = (unsigned)((krow * 72 + kq) * 2);
    auto issue_kv = [&](int t, int s) {
        const unsigned st = sb + 36864 + s * ASTG + kvd;
        const size_t r = kvb + (size_t)t * 64 * QKVS;
        CPA(st,                  g_sh + r + DIMX);      CPA(st + 16,             g_sh + r + DIMX + 8);
        CPA(st + 9216,           g_sl + r + DIMX);      CPA(st + 9216 + 16,      g_sl + r + DIMX + 8);
        CPA(st + 18432,          g_sh + r + 2 * DIMX);  CPA(st + 18432 + 16,     g_sh + r + 2 * DIMX + 8);
        CPA(st + 27648,          g_sl + r + 2 * DIMX);  CPA(st + 27648 + 16,     g_sl + r + 2 * DIMX + 8);
        CPA_COMMIT();
    };
    issue_kv(0, 0);
    __syncthreads();   // Q visible

    // ---- persistent Q-hi frags: qfh[rt][s] ----
    unsigned qfh[2][4][4];
    const unsigned qA0 = sb + (unsigned)((g * 32 + (lane & 15)) * 144 + (lane >> 4) * 16);
    const unsigned qA1 = qA0 + 16 * 144;
#pragma unroll
    for (int s = 0; s < 4; s++) {
        ldsm4(qfh[0][s], qA0 + s * 32);
        ldsm4(qfh[1][s], qA1 + s * 32);
    }

    float o[2][8][4];
#pragma unroll
    for (int rt = 0; rt < 2; rt++)
#pragma unroll
        for (int i = 0; i < 8; i++)
#pragma unroll
            for (int q = 0; q < 4; q++) o[rt][i][q] = 0.f;
    float lac[2][2] = {{0.f, 0.f}, {0.f, 0.f}};

    const unsigned kOff = (unsigned)((js * 32 + (lane & 7) + ((lane >> 4) << 3)) * 144 +
                                     ((lane >> 3) & 1) * 16);
    const unsigned vOff = 18432 + (unsigned)((js * 32 + (lane & 15)) * 144 + (lane >> 4) * 16);
    const unsigned pA0 = sb + 110592 + (unsigned)((g * 32 + (lane & 15)) * 144 +
                                                  (lane >> 4) * 16 + js * 64);
    const unsigned pA1 = pA0 + 16 * 144;
    const int r0 = g * 32 + (lane >> 2);
    const int pcol = js * 32 + (lane & 3) * 2;

    for (int t = 0; t < 32; t++) {
        if (t < 31) { issue_kv(t + 1, (t + 1) & 1); cpa_wait<1>(); }
        else        { cpa_wait<0>(); }
        __syncthreads();
        const unsigned st = sb + 36864 + (t & 1) * ASTG;
        const unsigned khA = st + kOff, klA = khA + 9216, vA = st + vOff;

        // ---- S = Q K^T ----
        float sacc[2][4][4];
#pragma unroll
        for (int rt = 0; rt < 2; rt++)
#pragma unroll
            for (int jt = 0; jt < 4; jt++)
#pragma unroll
                for (int q = 0; q < 4; q++) sacc[rt][jt][q] = 0.f;
#pragma unroll
        for (int s = 0; s < 4; s++) {
            unsigned k0h[4], k1h[4], k0l[4], k1l[4], ql0[4], ql1[4];
            ldsm4(k0h, khA + s * 32);
            ldsm4(k1h, khA + 16 * 144 + s * 32);
            ldsm4(k0l, klA + s * 32);
            ldsm4(k1l, klA + 16 * 144 + s * 32);
            ldsm4(ql0, qA0 + 18432 + s * 32);
            ldsm4(ql1, qA1 + 18432 + s * 32);
            mmab(sacc[0][0], qfh[0][s], k0h[0], k0h[1]);
            mmab(sacc[0][0], qfh[0][s], k0l[0], k0l[1]);
            mmab(sacc[0][0], ql0,       k0h[0], k0h[1]);
            mmab(sacc[0][1], qfh[0][s], k0h[2], k0h[3]);
            mmab(sacc[0][1], qfh[0][s], k0l[2], k0l[3]);
            mmab(sacc[0][1], ql0,       k0h[2], k0h[3]);
            mmab(sacc[0][2], qfh[0][s], k1h[0], k1h[1]);
            mmab(sacc[0][2], qfh[0][s], k1l[0], k1l[1]);
            mmab(sacc[0][2], ql0,       k1h[0], k1h[1]);
            mmab(sacc[0][3], qfh[0][s], k1h[2], k1h[3]);
            mmab(sacc[0][3], qfh[0][s], k1l[2], k1l[3]);
            mmab(sacc[0][3], ql0,       k1h[2], k1h[3]);
            mmab(sacc[1][0], qfh[1][s], k0h[0], k0h[1]);
            mmab(sacc[1][0], qfh[1][s], k0l[0], k0l[1]);
            mmab(sacc[1][0], ql1,       k0h[0], k0h[1]);
            mmab(sacc[1][1], qfh[1][s], k0h[2], k0h[3]);
            mmab(sacc[1][1], qfh[1][s], k0l[2], k0l[3]);
            mmab(sacc[1][1], ql1,       k0h[2], k0h[3]);
            mmab(sacc[1][2], qfh[1][s], k1h[0], k1h[1]);
            mmab(sacc[1][2], qfh[1][s], k1l[0], k1l[1]);
            mmab(sacc[1][2], ql1,       k1h[0], k1h[1]);
            mmab(sacc[1][3], qfh[1][s], k1h[2], k1h[3]);
            mmab(sacc[1][3], qfh[1][s], k1l[2], k1l[3]);
            mmab(sacc[1][3], ql1,       k1h[2], k1h[3]);
        }

        // ---- softmax (no max shift), split P to smem ----
#pragma unroll
        for (int rt = 0; rt < 2; rt++) {
            const int rr = r0 + rt * 16;
#pragma unroll
            for (int jt = 0; jt < 4; jt++) {
                float p0 = __expf(sacc[rt][jt][0]), p1 = __expf(sacc[rt][jt][1]);
                float p2 = __expf(sacc[rt][jt][2]), p3 = __expf(sacc[rt][jt][3]);
                lac[rt][0] += p0 + p1;
                lac[rt][1] += p2 + p3;
                __nv_bfloat162 hh, ll;
                split2(p0, p1, hh, ll);
                *(__nv_bfloat162*)(sm_raw + 110592 + (rr * 72 + pcol + jt * 8) * 2) = hh;
                *(__nv_bfloat162*)(sm_raw + 129024 + (rr * 72 + pcol + jt * 8) * 2) = ll;
                split2(p2, p3, hh, ll);
                *(__nv_bfloat162*)(sm_raw + 110592 + ((rr + 8) * 72 + pcol + jt * 8) * 2) = hh;
                *(__nv_bfloat162*)(sm_raw + 129024 + ((rr + 8) * 72 + pcol + jt * 8) * 2) = ll;
            }
        }
        __syncwarp();

        // ---- O += P V ----
#pragma unroll
        for (int sp = 0; sp < 2; sp++) {
            unsigned ph0[4], pl0[4], ph1[4], pl1[4];
            ldsm4(ph0, pA0 + sp * 32);
            ldsm4(pl0, pA0 + 18432 + sp * 32);
            ldsm4(ph1, pA1 + sp * 32);
            ldsm4(pl1, pA1 + 18432 + sp * 32);
#pragma unroll
            for (int db = 0; db < 4; db++) {
                unsigned vh[4], vl[4];
                ldsm4t(vh, vA + sp * 2304 + db * 32);
                ldsm4t(vl, vA + sp * 2304 + 9216 + db * 32);
                mmab(o[0][2 * db + 0], ph0, vh[0], vh[1]);
                mmab(o[0][2 * db + 0], ph0, vl[0], vl[1]);
                mmab(o[0][2 * db + 0], pl0, vh[0], vh[1]);
                mmab(o[0][2 * db + 1], ph0, vh[2], vh[3]);
                mmab(o[0][2 * db + 1], ph0, vl[2], vl[3]);
                mmab(o[0][2 * db + 1], pl0, vh[2], vh[3]);
                mmab(o[1][2 * db + 0], ph1, vh[0], vh[1]);
                mmab(o[1][2 * db + 0], ph1, vl[0], vl[1]);
                mmab(o[1][2 * db + 0], pl1, vh[0], vh[1]);
                mmab(o[1][2 * db + 1], ph1, vh[2], vh[3]);
                mmab(o[1][2 * db + 1], ph1, vl[2], vl[3]);
                mmab(o[1][2 * db + 1], pl1, vh[2], vh[3]);
            }
        }
        __syncthreads();
    }

    // ---- reduce l across quad ----
#pragma unroll
    for (int rt = 0; rt < 2; rt++)
#pragma unroll
        for (int hf = 0; hf < 2; hf++) {
            lac[rt][hf] += __shfl_xor_sync(0xffffffffu, lac[rt][hf], 1);
            lac[rt][hf] += __shfl_xor_sync(0xffffffffu, lac[rt][hf], 2);
        }

    // ---- cross-half (js) reduction via smem float scratch ----
    __syncthreads();
    float* red = (float*)sm_raw;                 // [128][68]
    float* redl = (float*)(sm_raw + 128 * 68 * 4);  // [128]
    if (js == 1) {
#pragma unroll
        for (int rt = 0; rt < 2; rt++) {
            const int rr = r0 + rt * 16;
#pragma unroll
            for (int dt = 0; dt < 8; dt++) {
                *(float2*)&red[rr * 68 + dt * 8 + (lane & 3) * 2] =
                    make_float2(o[rt][dt][0], o[rt][dt][1]);
                *(float2*)&red[(rr + 8) * 68 + dt * 8 + (lane & 3) * 2] =
                    make_float2(o[rt][dt][2], o[rt][dt][3]);
            }
            if ((lane & 3) == 0) { redl[rr] = lac[rt][0]; redl[rr + 8] = lac[rt][1]; }
        }
    }
    __syncthreads();
    if (js == 0) {
#pragma unroll
        for (int rt = 0; rt < 2; rt++) {
            const int rr = r0 + rt * 16;
            float inv0 = 1.f / (lac[rt][0] + redl[rr]);
            float inv1 = 1.f / (lac[rt][1] + redl[rr + 8]);
            float* op0 = out + ((size_t)(b * NSEQ + q0 + rr) * HH + h) * DD;
            float* op1 = out + ((size_t)(b * NSEQ + q0 + rr + 8) * HH + h) * DD;
#pragma unroll
            for (int dt = 0; dt < 8; dt++) {
                float2 e0 = *(const float2*)&red[rr * 68 + dt * 8 + (lane & 3) * 2];
                float2 e1 = *(const float2*)&red[(rr + 8) * 68 + dt * 8 + (lane & 3) * 2];
                *(float2*)&op0[dt * 8 + (lane & 3) * 2] =
                    make_float2((o[rt][dt][0] + e0.x) * inv0, (o[rt][dt][1] + e0.y) * inv0);
                *(float2*)&op1[dt * 8 + (lane & 3) * 2] =
                    make_float2((o[rt][dt][2] + e1.x) * inv1, (o[rt][dt][3] + e1.y) * inv1);
            }
        }
    }
}

// ---------------------------------------------------------------------------
extern "C" void kernel_launch(void* const* d_in, const int* in_sizes, int n_in,
                              void* d_out, int out_size) {
    (void)in_sizes; (void)n_in; (void)out_size;
    const float* x = (const float*)d_in[0];
    const float* w = (const float*)d_in[1];
    float* out = (float*)d_out;

    __nv_bfloat16 *xh, *xl, *wh, *wl;
    cudaGetSymbolAddress((void**)&xh, g_xh);
    cudaGetSymbolAddress((void**)&xl, g_xl);
    cudaGetSymbolAddress((void**)&wh, g_wh);
    cudaGetSymbolAddress((void**)&wl, g_wl);

    const int gemm_smem = 2 * GSTG;      // 81920
    const int attn_smem = 147456;
    cudaFuncSetAttribute((const void*)qkv_gemm,
                         cudaFuncAttributeMaxDynamicSharedMemorySize, gemm_smem);
    cudaFuncSetAttribute((const void*)attn,
                         cudaFuncAttributeMaxDynamicSharedMemorySize, attn_smem);

    split_kernel<<<(GM * GK / 4 + 255) / 256, 256>>>(x, xh, xl, GM * GK / 4);
    split_kernel<<<(GN * GK / 4 + 255) / 256, 256>>>(w, wh, wl, GN * GK / 4);

    dim3 g1(GN / 128, GM / 128);           // (24, 32)
    qkv_gemm<<<g1, 256, gemm_smem>>>();

    dim3 g2(NSEQ / 128, HH, BB);           // (16, 16, 2)
    attn<<<g2, 256, attn_smem>>>(out);
}